// round 14
// baseline (speedup 1.0000x reference)
#include <cuda_runtime.h>
#include <cstdint>
#include <math.h>

// ---------------- problem constants ----------------
#define NROWS 8192
#define DDIM  1024            // features per row; 1024 bytes per int8 row
#define BM 128
#define BN 128
#define BK 128                // k bytes per chunk = one 128-byte swizzled row
#define NCHUNK (DDIM / BK)    // 8
#define NSTAGE 3
#define THREADS 128           // 4 warps, each 64x64 output tile

static __device__ __constant__ float kTempInv = 14.2857142857142857f;  // 1/0.07

// ---------------- scratch (no runtime allocation) ----------------
__device__ signed char g_qa[(size_t)NROWS * DDIM];   // quantized normalized A
__device__ signed char g_qb[(size_t)NROWS * DDIM];   // quantized normalized B
__device__ float g_sa[NROWS];                        // per-row dequant scale A
__device__ float g_sb[NROWS];                        // per-row dequant scale B
__device__ double g_pos[NROWS];
__device__ double g_neg[NROWS];
__device__ double g_loss;

// ---------------- SMEM layout ----------------
#define A_BYTES (BM * 128)            // 16384
#define B_BYTES (BN * 128)            // 16384
#define STAGE_B (A_BYTES + B_BYTES)   // 32768
#define AUX_BASE (NSTAGE * STAGE_B)   // 98304
#define AUX_SLA  (AUX_BASE)           // 128*4
#define AUX_SLB  (AUX_BASE + 512)
#define AUX_SSA  (AUX_BASE + 1024)    // row scales
#define AUX_SSB  (AUX_BASE + 1536)    // col scales
#define AUX_SPOS (AUX_BASE + 2048)
#define AUX_SNEG (AUX_BASE + 2560)
#define SMEM_TOTAL (AUX_BASE + 3072)  // 101376 (x2 CTAs <= 228KB)

#define SWZ(o) ((o) ^ (((o) >> 3) & 0x70))

__device__ __forceinline__ uint32_t smem_u32(const void* p) {
    uint32_t a;
    asm("{ .reg .u64 t; cvta.to.shared.u64 t, %1; cvt.u32.u64 %0, t; }"
        : "=r"(a) : "l"(p));
    return a;
}

#define LDSM_X4(r0, r1, r2, r3, addr) \
    asm volatile("ldmatrix.sync.aligned.m8n8.x4.shared.b16 {%0,%1,%2,%3}, [%4];" \
                 : "=r"(r0), "=r"(r1), "=r"(r2), "=r"(r3) : "r"(addr))

// int8 MMA, k=32 per instruction, exact int32 accumulate
#define MMA_S8(c, a, b0, b1) \
    asm volatile("mma.sync.aligned.m16n8k32.row.col.s32.s8.s8.s32 " \
                 "{%0,%1,%2,%3}, {%4,%5,%6,%7}, {%8,%9}, {%0,%1,%2,%3};" \
                 : "+r"((c)[0]), "+r"((c)[1]), "+r"((c)[2]), "+r"((c)[3]) \
                 : "r"((a)[0]), "r"((a)[1]), "r"((a)[2]), "r"((a)[3]), \
                   "r"(b0), "r"(b1))

#define CP_ASYNC16(dst, src) \
    asm volatile("cp.async.cg.shared.global [%0], [%1], 16;" :: "r"(dst), "l"(src))
#define CP_COMMIT() asm volatile("cp.async.commit_group;" ::: "memory")

// ---------------------------------------------------------------------------
// L2 normalize + per-row int8 quantization + accumulator zeroing.
// 2*NROWS blocks, 256 threads, 4 floats/thread.
//   q_i = round(x_i * 127 / max|x|),  scale = max|x| / (norm * 127)
// so scale * q ≈ x / norm (the normalized value).
// ---------------------------------------------------------------------------
__global__ void normalize_kernel(const float* __restrict__ A,
                                 const float* __restrict__ B) {
    int row = blockIdx.x;
    const float* src;
    signed char* dst;
    float* srow;
    int srow_idx;
    if (row < NROWS) {
        src = A + (size_t)row * DDIM;
        dst = g_qa + (size_t)row * DDIM;
        srow = g_sa; srow_idx = row;
        if (threadIdx.x == 0) { g_pos[row] = 0.0; g_neg[row] = 0.0; }
        if (row == 0 && threadIdx.x == 1) g_loss = 0.0;
    } else {
        int r = row - NROWS;
        src = B + (size_t)r * DDIM;
        dst = g_qb + (size_t)r * DDIM;
        srow = g_sb; srow_idx = r;
    }
    int t = threadIdx.x;
    float4 v = reinterpret_cast<const float4*>(src)[t];
    float s = v.x * v.x + v.y * v.y + v.z * v.z + v.w * v.w;
    float m = fmaxf(fmaxf(fabsf(v.x), fabsf(v.y)),
                    fmaxf(fabsf(v.z), fabsf(v.w)));
    #pragma unroll
    for (int off = 16; off > 0; off >>= 1) {
        s += __shfl_xor_sync(0xffffffffu, s, off);
        m = fmaxf(m, __shfl_xor_sync(0xffffffffu, m, off));
    }
    __shared__ float ws[8], wmx[8];
    if ((t & 31) == 0) { ws[t >> 5] = s; wmx[t >> 5] = m; }
    __syncthreads();
    if (t < 32) {
        float x = (t < 8) ? ws[t] : 0.0f;
        float y = (t < 8) ? wmx[t] : 0.0f;
        #pragma unroll
        for (int off = 4; off > 0; off >>= 1) {
            x += __shfl_xor_sync(0xffffffffu, x, off);
            y = fmaxf(y, __shfl_xor_sync(0xffffffffu, y, off));
        }
        if (t == 0) { ws[0] = x; wmx[0] = y; }
    }
    __syncthreads();
    float norm = fmaxf(sqrtf(ws[0]), 1e-12f);
    float mx   = fmaxf(wmx[0], 1e-20f);
    float qs   = 127.0f / mx;              // quantize factor (pre-norm values)
    if (t == 0) srow[srow_idx] = mx / (norm * 127.0f);

    int q0 = __float2int_rn(v.x * qs);
    int q1 = __float2int_rn(v.y * qs);
    int q2 = __float2int_rn(v.z * qs);
    int q3 = __float2int_rn(v.w * qs);
    uint32_t packed = (uint32_t)(q0 & 0xff) | ((uint32_t)(q1 & 0xff) << 8) |
                      ((uint32_t)(q2 & 0xff) << 16) | ((uint32_t)q3 << 24);
    reinterpret_cast<uint32_t*>(dst)[t] = packed;
}

// ---------------------------------------------------------------------------
// int8 IMMA GEMM: 128x128 CTA, 4 warps of 64x64, 2 CTAs/SM, 3-stage ring.
// Byte-addressing identical to the fp16 version: 128-byte swizzled rows;
// cb = ks*32 bytes now covers k=32 int8 per mma (vs 16 fp16).
// ---------------------------------------------------------------------------
extern __shared__ __align__(1024) char smem[];

template <bool PRE>
__device__ __forceinline__ void compute_chunk(uint32_t aBase, uint32_t bBase,
                                              int (&acc)[4][8][4],
                                              uint32_t dstA, uint32_t dstB,
                                              const signed char* srcA,
                                              const signed char* srcB) {
    #pragma unroll
    for (int ks = 0; ks < 4; ks++) {
        if (PRE) {  // 4 of the 16 prefetch cp.asyncs per ks-step (2 A + 2 B)
            CP_ASYNC16(dstA + (ks * 2 + 0) * 2048,
                       srcA + (size_t)(ks * 2 + 0) * 16 * DDIM);
            CP_ASYNC16(dstA + (ks * 2 + 1) * 2048,
                       srcA + (size_t)(ks * 2 + 1) * 16 * DDIM);
            CP_ASYNC16(dstB + (ks * 2 + 0) * 2048,
                       srcB + (size_t)(ks * 2 + 0) * 16 * DDIM);
            CP_ASYNC16(dstB + (ks * 2 + 1) * 2048,
                       srcB + (size_t)(ks * 2 + 1) * 16 * DDIM);
        }
        const uint32_t cb = ks * 32;   // XOR byte-offset within swizzled row
        uint32_t a[4][4];
        #pragma unroll
        for (int i = 0; i < 4; i++)
            LDSM_X4(a[i][0], a[i][1], a[i][2], a[i][3],
                    (aBase + i * 2048) ^ cb);
        #pragma unroll
        for (int j = 0; j < 4; j++) {
            uint32_t b0, b1, b2, b3;
            LDSM_X4(b0, b1, b2, b3, (bBase + j * 2048) ^ cb);
            #pragma unroll
            for (int i = 0; i < 4; i++) {
                MMA_S8(acc[i][j * 2 + 0], a[i], b0, b2);
                MMA_S8(acc[i][j * 2 + 1], a[i], b1, b3);
            }
        }
    }
    if (PRE) CP_COMMIT();
}

__global__ __launch_bounds__(THREADS, 2)
void gemm_mma_kernel(const int* __restrict__ la, const int* __restrict__ lb) {
    const int tid  = threadIdx.x;
    const int lane = tid & 31;
    const int wid  = tid >> 5;
    const int wm   = wid >> 1;       // 2 warps along M
    const int wn   = wid & 1;        // 2 warps along N
    const int bm0  = blockIdx.y * BM;
    const int bn0  = blockIdx.x * BN;

    int* sla = (int*)(smem + AUX_SLA);
    int* slb = (int*)(smem + AUX_SLB);
    float* ssa = (float*)(smem + AUX_SSA);
    float* ssb = (float*)(smem + AUX_SSB);
    float* spos = (float*)(smem + AUX_SPOS);
    float* sneg = (float*)(smem + AUX_SNEG);

    sla[tid] = la[bm0 + tid];
    slb[tid] = lb[bn0 + tid];
    ssa[tid] = g_sa[bm0 + tid];
    ssb[tid] = g_sb[bn0 + tid];
    spos[tid] = 0.0f;
    sneg[tid] = 0.0f;

    uint32_t sbase = smem_u32(smem);

    // ---- per-thread cp.async offsets (row = tid>>3 in [0,16), u = tid&7) ----
    const int ld_r = tid >> 3;
    const int ld_u = tid & 7;
    const uint32_t ld_off = SWZ(ld_r * 128 + ld_u * 16);  // +16 rows -> +2048
    const signed char* srcA = g_qa + (size_t)(bm0 + ld_r) * DDIM + ld_u * 16;
    const signed char* srcB = g_qb + (size_t)(bn0 + ld_r) * DDIM + ld_u * 16;

    // ---- per-thread ldsm base addresses ----
    const int rl = lane & 15;
    const int ch = lane >> 4;
    const int ar0 = wm * 64 + rl;
    const int br0 = wn * 64 + rl;
    const uint32_t chx = (uint32_t)(ch * 16);
    const uint32_t aOff0 = (uint32_t)(ar0 * 128) + (((uint32_t)(ar0 & 7) * 16) ^ chx);
    const uint32_t bOff0 = (uint32_t)(br0 * 128) + (((uint32_t)(br0 & 7) * 16) ^ chx);

    int acc[4][8][4];
    #pragma unroll
    for (int i = 0; i < 4; i++)
        #pragma unroll
        for (int j = 0; j < 8; j++)
            #pragma unroll
            for (int v = 0; v < 4; v++)
                acc[i][j][v] = 0;

    // prologue: chunks 0 and 1 in flight
    #pragma unroll
    for (int s = 0; s < 2; s++) {
        uint32_t dA = sbase + s * STAGE_B + ld_off;
        uint32_t dB = dA + A_BYTES;
        #pragma unroll
        for (int it = 0; it < 8; it++) {
            CP_ASYNC16(dA + it * 2048, srcA + s * BK + (size_t)it * 16 * DDIM);
            CP_ASYNC16(dB + it * 2048, srcB + s * BK + (size_t)it * 16 * DDIM);
        }
        CP_COMMIT();
    }

    // one sync per chunk; prefetch depth 2 over 3 buffers, loads interleaved.
    #pragma unroll 1
    for (int c = 0; c < NCHUNK - 2; c++) {
        asm volatile("cp.async.wait_group 1;" ::: "memory");
        __syncthreads();
        uint32_t aB = sbase + (c % NSTAGE) * STAGE_B;
        uint32_t st = ((c + 2) % NSTAGE) * STAGE_B;
        compute_chunk<true>(aB + aOff0, aB + A_BYTES + bOff0, acc,
                            sbase + st + ld_off, sbase + st + A_BYTES + ld_off,
                            srcA + (c + 2) * BK, srcB + (c + 2) * BK);
    }
    {   // chunk NCHUNK-2: pending {NCHUNK-2, NCHUNK-1}
        asm volatile("cp.async.wait_group 1;" ::: "memory");
        __syncthreads();
        uint32_t aB = sbase + ((NCHUNK - 2) % NSTAGE) * STAGE_B;
        compute_chunk<false>(aB + aOff0, aB + A_BYTES + bOff0, acc,
                             0, 0, nullptr, nullptr);
    }
    {   // last chunk
        asm volatile("cp.async.wait_group 0;" ::: "memory");
        __syncthreads();
        uint32_t aB = sbase + ((NCHUNK - 1) % NSTAGE) * STAGE_B;
        compute_chunk<false>(aB + aOff0, aB + A_BYTES + bOff0, acc,
                             0, 0, nullptr, nullptr);
    }

    // ----- epilogue: dequant + exp + label mask + row sums -----
    const int g  = lane >> 2;
    const int t4 = lane & 3;

    int rowlab[8];
    float rowsc[8];
    #pragma unroll
    for (int i = 0; i < 4; i++) {
        int r0 = wm * 64 + i * 16 + g;
        rowlab[2 * i + 0] = sla[r0];
        rowlab[2 * i + 1] = sla[r0 + 8];
        rowsc[2 * i + 0] = ssa[r0] * kTempInv;
        rowsc[2 * i + 1] = ssa[r0 + 8] * kTempInv;
    }
    int collab[16];
    float colsc[16];
    #pragma unroll
    for (int j = 0; j < 8; j++) {
        int c0 = wn * 64 + j * 8 + t4 * 2;
        collab[2 * j + 0] = slb[c0];
        collab[2 * j + 1] = slb[c0 + 1];
        colsc[2 * j + 0] = ssb[c0];
        colsc[2 * j + 1] = ssb[c0 + 1];
    }

    float prow[8], nrow[8];
    #pragma unroll
    for (int k = 0; k < 8; k++) { prow[k] = 0.0f; nrow[k] = 0.0f; }

    #pragma unroll
    for (int i = 0; i < 4; i++)
        #pragma unroll
        for (int j = 0; j < 8; j++)
            #pragma unroll
            for (int v = 0; v < 4; v++) {
                int h = v >> 1;
                float sim = (float)acc[i][j][v] * rowsc[2 * i + h] *
                            colsc[2 * j + (v & 1)];
                float e = __expf(sim);
                nrow[2 * i + h] += e;
                if (collab[2 * j + (v & 1)] == rowlab[2 * i + h])
                    prow[2 * i + h] += e;
            }

    #pragma unroll
    for (int off = 1; off <= 2; off <<= 1)
        #pragma unroll
        for (int k = 0; k < 8; k++) {
            prow[k] += __shfl_xor_sync(0xffffffffu, prow[k], off);
            nrow[k] += __shfl_xor_sync(0xffffffffu, nrow[k], off);
        }

    if (t4 == 0) {
        #pragma unroll
        for (int k = 0; k < 8; k++) {
            int row = wm * 64 + (k >> 1) * 16 + g + (k & 1) * 8;
            atomicAdd(&spos[row], prow[k]);
            atomicAdd(&sneg[row], nrow[k]);
        }
    }
    __syncthreads();
    atomicAdd(&g_pos[bm0 + tid], (double)spos[tid]);
    atomicAdd(&g_neg[bm0 + tid], (double)sneg[tid]);
}

// ---------------------------------------------------------------------------
// finalize stage 1: 16 blocks x 512 threads, partial sums -> atomic double
// ---------------------------------------------------------------------------
__global__ void finalize1_kernel() {
    int t = blockIdx.x * blockDim.x + threadIdx.x;
    double p = g_pos[t];
    if (p < 1e-8) p = 1e-8;
    double local = (double)logf((float)(p / g_neg[t]));
    #pragma unroll
    for (int off = 16; off > 0; off >>= 1)
        local += __shfl_xor_sync(0xffffffffu, local, off);
    __shared__ double ws[16];
    int lt = threadIdx.x;
    if ((lt & 31) == 0) ws[lt >> 5] = local;
    __syncthreads();
    if (lt < 16) {
        double x = ws[lt];
        #pragma unroll
        for (int off = 8; off > 0; off >>= 1)
            x += __shfl_xor_sync(0xffffffffu, x, off);
        if (lt == 0) atomicAdd(&g_loss, x);
    }
}

__global__ void finalize2_kernel(float* __restrict__ out) {
    out[0] = (float)(-g_loss / (double)NROWS);
}

// ---------------------------------------------------------------------------
extern "C" void kernel_launch(void* const* d_in, const int* in_sizes, int n_in,
                              void* d_out, int out_size) {
    const float* fa = (const float*)d_in[0];
    const float* fb = (const float*)d_in[1];
    const int*   la = (const int*)d_in[2];
    const int*   lb = (const int*)d_in[3];
    float* out = (float*)d_out;

    cudaFuncSetAttribute(gemm_mma_kernel,
                         cudaFuncAttributeMaxDynamicSharedMemorySize, SMEM_TOTAL);

    normalize_kernel<<<2 * NROWS, 256>>>(fa, fb);
    dim3 grid(NROWS / BN, NROWS / BM);
    gemm_mma_kernel<<<grid, THREADS, SMEM_TOTAL>>>(la, lb);
    finalize1_kernel<<<16, 512>>>();
    finalize2_kernel<<<1, 1>>>(out);
}

// round 16
// speedup vs baseline: 2.6090x; 2.6090x over previous
#include <cuda_runtime.h>
#include <cuda_fp16.h>
#include <cstdint>
#include <math.h>

// ---------------- problem constants ----------------
#define NROWS 8192
#define DDIM  1024
#define BM 128
#define BN 128
#define BK 64                 // k elems per chunk = 128 bytes/row
#define NCHUNK (DDIM / BK)    // 16
#define NSTAGE 3
#define THREADS 256

// (1/0.07) * log2(e): fold temperature and exp->exp2 conversion into one factor
static __device__ __constant__ float kTempInvLog2e = 20.6099131838246f;

// ---------------- scratch (no runtime allocation) ----------------
__device__ __half g_fa[(size_t)NROWS * DDIM];   // normalized A, fp16
__device__ __half g_fb[(size_t)NROWS * DDIM];   // normalized B, fp16
__device__ double g_pos[NROWS];
__device__ double g_neg[NROWS];
__device__ double g_loss;

// ---------------- SMEM layout ----------------
#define A_BYTES (BM * 128)            // 16384
#define B_BYTES (BN * 128)            // 16384
#define STAGE_B (A_BYTES + B_BYTES)   // 32768
#define AUX_BASE (NSTAGE * STAGE_B)   // 98304
#define AUX_SLA  (AUX_BASE)           // 128*4
#define AUX_SLB  (AUX_BASE + 512)     // 128*4
#define AUX_SPOS (AUX_BASE + 1024)    // 128*4
#define AUX_SNEG (AUX_BASE + 1536)    // 128*4
#define SMEM_TOTAL (AUX_BASE + 2048)  // 100352  (x2 CTAs = 200704 <= 228KB)

#define SWZ(o) ((o) ^ (((o) >> 3) & 0x70))

__device__ __forceinline__ uint32_t smem_u32(const void* p) {
    uint32_t a;
    asm("{ .reg .u64 t; cvta.to.shared.u64 t, %1; cvt.u32.u64 %0, t; }"
        : "=r"(a) : "l"(p));
    return a;
}

#define LDSM_X4(r0, r1, r2, r3, addr) \
    asm volatile("ldmatrix.sync.aligned.m8n8.x4.shared.b16 {%0,%1,%2,%3}, [%4];" \
                 : "=r"(r0), "=r"(r1), "=r"(r2), "=r"(r3) : "r"(addr))

#define MMA16816(c, a, b0, b1) \
    asm volatile("mma.sync.aligned.m16n8k16.row.col.f32.f16.f16.f32 " \
                 "{%0,%1,%2,%3}, {%4,%5,%6,%7}, {%8,%9}, {%0,%1,%2,%3};" \
                 : "+f"((c)[0]), "+f"((c)[1]), "+f"((c)[2]), "+f"((c)[3]) \
                 : "r"((a)[0]), "r"((a)[1]), "r"((a)[2]), "r"((a)[3]), \
                   "r"(b0), "r"(b1))

#define CP_ASYNC16(dst, src) \
    asm volatile("cp.async.cg.shared.global [%0], [%1], 16;" :: "r"(dst), "l"(src))
#define CP_COMMIT() asm volatile("cp.async.commit_group;" ::: "memory")

// ---------------------------------------------------------------------------
// L2 normalize + fp16 convert + accumulator zeroing.
// 2*NROWS blocks, 256 threads, 4 floats/thread.
// ---------------------------------------------------------------------------
__global__ void normalize_kernel(const float* __restrict__ A,
                                 const float* __restrict__ B) {
    int row = blockIdx.x;
    const float* src;
    __half* dst;
    if (row < NROWS) {
        src = A + (size_t)row * DDIM;
        dst = g_fa + (size_t)row * DDIM;
        if (threadIdx.x == 0) { g_pos[row] = 0.0; g_neg[row] = 0.0; }
        if (row == 0 && threadIdx.x == 1) g_loss = 0.0;
    } else {
        int r = row - NROWS;
        src = B + (size_t)r * DDIM;
        dst = g_fb + (size_t)r * DDIM;
    }
    int t = threadIdx.x;
    float4 v = reinterpret_cast<const float4*>(src)[t];
    float s = v.x * v.x + v.y * v.y + v.z * v.z + v.w * v.w;
    #pragma unroll
    for (int off = 16; off > 0; off >>= 1)
        s += __shfl_xor_sync(0xffffffffu, s, off);
    __shared__ float ws[8];
    if ((t & 31) == 0) ws[t >> 5] = s;
    __syncthreads();
    if (t < 32) {
        float x = (t < 8) ? ws[t] : 0.0f;
        #pragma unroll
        for (int off = 4; off > 0; off >>= 1)
            x += __shfl_xor_sync(0xffffffffu, x, off);
        if (t == 0) ws[0] = x;
    }
    __syncthreads();
    float scale = 1.0f / fmaxf(sqrtf(ws[0]), 1e-12f);

    __half2 h0 = __floats2half2_rn(v.x * scale, v.y * scale);
    __half2 h1 = __floats2half2_rn(v.z * scale, v.w * scale);
    __half2* p = reinterpret_cast<__half2*>(dst + t * 4);
    p[0] = h0;
    p[1] = h1;
}

// ---------------------------------------------------------------------------
// fp16 mma.sync GEMM (128x128 CTA tile, 2 CTAs/SM) + fused exp/mask epilogue
// Prefetch cp.asyncs interleaved into the compute (2 per ks-step) to avoid
// post-barrier front-batched load bursts (cross-CTA L1tex contention).
// ---------------------------------------------------------------------------
extern __shared__ __align__(1024) char smem[];

// warp tile 32(M) x 64(N): wm = wid>>1 (0..3), wn = wid&1 (0..1)
template <bool PRE>
__device__ __forceinline__ void compute_chunk(uint32_t aBase0, uint32_t aBase1,
                                              uint32_t bBase0, uint32_t bBase1,
                                              uint32_t bBase2, uint32_t bBase3,
                                              float (&acc)[2][8][4],
                                              uint32_t dstA, uint32_t dstB,
                                              const __half* srcA,
                                              const __half* srcB) {
    #pragma unroll
    for (int ks = 0; ks < 4; ks++) {
        if (PRE) {  // 2 of the 8 prefetch cp.asyncs per ks-step
            CP_ASYNC16(dstA + ks * 4096, srcA + (size_t)ks * 32 * DDIM);
            CP_ASYNC16(dstB + ks * 4096, srcB + (size_t)ks * 32 * DDIM);
        }
        const uint32_t cb = ks * 32;   // XOR-offset within swizzled row
        uint32_t a[2][4];
        LDSM_X4(a[0][0], a[0][1], a[0][2], a[0][3], aBase0 ^ cb);
        LDSM_X4(a[1][0], a[1][1], a[1][2], a[1][3], aBase1 ^ cb);
        uint32_t b0, b1, b2, b3;
        LDSM_X4(b0, b1, b2, b3, bBase0 ^ cb);
        MMA16816(acc[0][0], a[0], b0, b2);
        MMA16816(acc[0][1], a[0], b1, b3);
        MMA16816(acc[1][0], a[1], b0, b2);
        MMA16816(acc[1][1], a[1], b1, b3);
        LDSM_X4(b0, b1, b2, b3, bBase1 ^ cb);
        MMA16816(acc[0][2], a[0], b0, b2);
        MMA16816(acc[0][3], a[0], b1, b3);
        MMA16816(acc[1][2], a[1], b0, b2);
        MMA16816(acc[1][3], a[1], b1, b3);
        LDSM_X4(b0, b1, b2, b3, bBase2 ^ cb);
        MMA16816(acc[0][4], a[0], b0, b2);
        MMA16816(acc[0][5], a[0], b1, b3);
        MMA16816(acc[1][4], a[1], b0, b2);
        MMA16816(acc[1][5], a[1], b1, b3);
        LDSM_X4(b0, b1, b2, b3, bBase3 ^ cb);
        MMA16816(acc[0][6], a[0], b0, b2);
        MMA16816(acc[0][7], a[0], b1, b3);
        MMA16816(acc[1][6], a[1], b0, b2);
        MMA16816(acc[1][7], a[1], b1, b3);
    }
    if (PRE) CP_COMMIT();
}

__global__ __launch_bounds__(THREADS, 2)
void gemm_mma_kernel(const int* __restrict__ la, const int* __restrict__ lb) {
    const int tid  = threadIdx.x;
    const int lane = tid & 31;
    const int wid  = tid >> 5;
    const int wm   = wid >> 1;       // 4 warps along M (32 rows each)
    const int wn   = wid & 1;        // 2 warps along N (64 cols each)
    const int bm0  = blockIdx.y * BM;
    const int bn0  = blockIdx.x * BN;

    int* sla = (int*)(smem + AUX_SLA);
    int* slb = (int*)(smem + AUX_SLB);
    float* spos = (float*)(smem + AUX_SPOS);
    float* sneg = (float*)(smem + AUX_SNEG);

    if (tid < BM) {
        sla[tid] = la[bm0 + tid];
        slb[tid] = lb[bn0 + tid];
        spos[tid] = 0.0f;
        sneg[tid] = 0.0f;
    }

    uint32_t sbase = smem_u32(smem);

    // ---- per-thread cp.async offsets (row = tid>>3 in [0,32), u = tid&7) ----
    const int ld_r = tid >> 3;
    const int ld_u = tid & 7;
    const uint32_t ld_off = SWZ(ld_r * 128 + ld_u * 16);
    const __half* srcA = g_fa + (size_t)(bm0 + ld_r) * DDIM + ld_u * 8;
    const __half* srcB = g_fb + (size_t)(bn0 + ld_r) * DDIM + ld_u * 8;

    // ---- per-thread ldsm base addresses ----
    // SWZ(row*128 + cb) == row*128 + (cb ^ (row&7)*16) for cb in bits [4:7)
    // A warp tile = 32 rows at wm*32; B warp tile = 64 rows at wn*64.
    const int rl = lane & 15;
    const int ch = lane >> 4;
    const int ar0 = wm * 32 + rl;
    const int ar1 = wm * 32 + 16 + rl;
    const int br0 = wn * 64 + rl;
    const uint32_t chx = (uint32_t)(ch * 16);
    const uint32_t aOff0 = (uint32_t)(ar0 * 128) + (((uint32_t)(ar0 & 7) * 16) ^ chx);
    const uint32_t aOff1 = (uint32_t)(ar1 * 128) + (((uint32_t)(ar1 & 7) * 16) ^ chx);
    const uint32_t bOff0 = (uint32_t)(br0 * 128) + (((uint32_t)(br0 & 7) * 16) ^ chx);
    const uint32_t bStep = 16 * 128;   // row&7 repeats every 16 rows

    float acc[2][8][4];
    #pragma unroll
    for (int i = 0; i < 2; i++)
        #pragma unroll
        for (int j = 0; j < 8; j++)
            #pragma unroll
            for (int v = 0; v < 4; v++)
                acc[i][j][v] = 0.0f;

    // prologue: chunks 0 and 1 in flight (pipeline fill; bursts OK here)
    {
        uint32_t dA0 = sbase + ld_off, dB0 = sbase + A_BYTES + ld_off;
        #pragma unroll
        for (int it = 0; it < 4; it++) {
            CP_ASYNC16(dA0 + it * 4096, srcA + (size_t)it * 32 * DDIM);
            CP_ASYNC16(dB0 + it * 4096, srcB + (size_t)it * 32 * DDIM);
        }
        CP_COMMIT();
        uint32_t dA1 = dA0 + STAGE_B, dB1 = dB0 + STAGE_B;
        #pragma unroll
        for (int it = 0; it < 4; it++) {
            CP_ASYNC16(dA1 + it * 4096, srcA + BK + (size_t)it * 32 * DDIM);
            CP_ASYNC16(dB1 + it * 4096, srcB + BK + (size_t)it * 32 * DDIM);
        }
        CP_COMMIT();
    }

    // one sync per chunk; prefetch depth 2 over 3 buffers, loads interleaved
    // into compute. iter c: pending groups {c, c+1}; wait_group 1 retires c.
    // chunk c+2 -> buffer (c+2)%3 == buffer consumed at iter c-1 (all readers
    // passed this iteration's barrier).
    #pragma unroll 1
    for (int c = 0; c < NCHUNK - 2; c++) {
        asm volatile("cp.async.wait_group 1;" ::: "memory");
        __syncthreads();
        uint32_t aB = sbase + (c % NSTAGE) * STAGE_B;
        uint32_t bB = aB + A_BYTES;
        uint32_t st = ((c + 2) % NSTAGE) * STAGE_B;
        compute_chunk<true>(aB + aOff0, aB + aOff1,
                            bB + bOff0, bB + bOff0 + bStep,
                            bB + bOff0 + 2 * bStep, bB + bOff0 + 3 * bStep, acc,
                            sbase + st + ld_off, sbase + st + A_BYTES + ld_off,
                            srcA + (c + 2) * BK, srcB + (c + 2) * BK);
    }
    {   // chunk 14: pending {14, 15}
        asm volatile("cp.async.wait_group 1;" ::: "memory");
        __syncthreads();
        uint32_t aB = sbase + ((NCHUNK - 2) % NSTAGE) * STAGE_B;
        uint32_t bB = aB + A_BYTES;
        compute_chunk<false>(aB + aOff0, aB + aOff1,
                             bB + bOff0, bB + bOff0 + bStep,
                             bB + bOff0 + 2 * bStep, bB + bOff0 + 3 * bStep, acc,
                             0, 0, nullptr, nullptr);
    }
    {   // chunk 15: pending {15}
        asm volatile("cp.async.wait_group 0;" ::: "memory");
        __syncthreads();
        uint32_t aB = sbase + ((NCHUNK - 1) % NSTAGE) * STAGE_B;
        uint32_t bB = aB + A_BYTES;
        compute_chunk<false>(aB + aOff0, aB + aOff1,
                             bB + bOff0, bB + bOff0 + bStep,
                             bB + bOff0 + 2 * bStep, bB + bOff0 + 3 * bStep, acc,
                             0, 0, nullptr, nullptr);
    }

    // ----- epilogue: exp + label mask + row sums -----
    // clip to [-50,50] omitted: |sim| <= 1/0.07 = 14.29 for unit rows.
    // exp(sim) computed as exp2(acc * (kTempInv*log2e)) -- one mul + MUFU.EX2.
    const int g  = lane >> 2;
    const int t4 = lane & 3;

    int rowlab[4];
    #pragma unroll
    for (int i = 0; i < 2; i++) {
        rowlab[2 * i + 0] = sla[wm * 32 + i * 16 + g];
        rowlab[2 * i + 1] = sla[wm * 32 + i * 16 + g + 8];
    }
    int collab[16];
    #pragma unroll
    for (int j = 0; j < 8; j++) {
        collab[2 * j + 0] = slb[wn * 64 + j * 8 + t4 * 2 + 0];
        collab[2 * j + 1] = slb[wn * 64 + j * 8 + t4 * 2 + 1];
    }

    float prow[4], nrow[4];
    #pragma unroll
    for (int k = 0; k < 4; k++) { prow[k] = 0.0f; nrow[k] = 0.0f; }

    #pragma unroll
    for (int i = 0; i < 2; i++)
        #pragma unroll
        for (int j = 0; j < 8; j++)
            #pragma unroll
            for (int v = 0; v < 4; v++) {
                float e = exp2f(acc[i][j][v] * kTempInvLog2e);
                int h = v >> 1;
                nrow[2 * i + h] += e;
                if (collab[2 * j + (v & 1)] == rowlab[2 * i + h])
                    prow[2 * i + h] += e;
            }

    // reduce across the 4 lanes of each quad (same row, different cols)
    #pragma unroll
    for (int off = 1; off <= 2; off <<= 1)
        #pragma unroll
        for (int k = 0; k < 4; k++) {
            prow[k] += __shfl_xor_sync(0xffffffffu, prow[k], off);
            nrow[k] += __shfl_xor_sync(0xffffffffu, nrow[k], off);
        }

    if (t4 == 0) {
        #pragma unroll
        for (int k = 0; k < 4; k++) {
            int row = wm * 32 + (k >> 1) * 16 + g + (k & 1) * 8;
            atomicAdd(&spos[row], prow[k]);
            atomicAdd(&sneg[row], nrow[k]);
        }
    }
    __syncthreads();
    if (tid < BM) {
        atomicAdd(&g_pos[bm0 + tid], (double)spos[tid]);
        atomicAdd(&g_neg[bm0 + tid], (double)sneg[tid]);
    }
}

// ---------------------------------------------------------------------------
// finalize stage 1: 16 blocks x 512 threads, partial sums -> atomic double
// ---------------------------------------------------------------------------
__global__ void finalize1_kernel() {
    int t = blockIdx.x * blockDim.x + threadIdx.x;  // 8192 threads total
    double p = g_pos[t];
    if (p < 1e-8) p = 1e-8;
    double local = (double)logf((float)(p / g_neg[t]));
    #pragma unroll
    for (int off = 16; off > 0; off >>= 1)
        local += __shfl_xor_sync(0xffffffffu, local, off);
    __shared__ double ws[16];
    int lt = threadIdx.x;
    if ((lt & 31) == 0) ws[lt >> 5] = local;
    __syncthreads();
    if (lt < 16) {
        double x = ws[lt];
        #pragma unroll
        for (int off = 8; off > 0; off >>= 1)
            x += __shfl_xor_sync(0xffffffffu, x, off);
        if (lt == 0) atomicAdd(&g_loss, x);
    }
}

__global__ void finalize2_kernel(float* __restrict__ out) {
    out[0] = (float)(-g_loss / (double)NROWS);
}

// ---------------------------------------------------------------------------
extern "C" void kernel_launch(void* const* d_in, const int* in_sizes, int n_in,
                              void* d_out, int out_size) {
    const float* fa = (const float*)d_in[0];
    const float* fb = (const float*)d_in[1];
    const int*   la = (const int*)d_in[2];
    const int*   lb = (const int*)d_in[3];
    float* out = (float*)d_out;

    cudaFuncSetAttribute(gemm_mma_kernel,
                         cudaFuncAttributeMaxDynamicSharedMemorySize, SMEM_TOTAL);

    normalize_kernel<<<2 * NROWS, 256>>>(fa, fb);
    dim3 grid(NROWS / BN, NROWS / BM);
    gemm_mma_kernel<<<grid, THREADS, SMEM_TOTAL>>>(la, lb);
    finalize1_kernel<<<16, 512>>>();
    finalize2_kernel<<<1, 1>>>(out);
}

// round 17
// speedup vs baseline: 2.6366x; 1.0106x over previous
#include <cuda_runtime.h>
#include <cuda_fp16.h>
#include <cstdint>
#include <math.h>

// ---------------- problem constants ----------------
#define NROWS 8192
#define DDIM  1024
#define BM 128
#define BN 128
#define BK 64                 // k elems per chunk = 128 bytes/row
#define NCHUNK (DDIM / BK)    // 16
#define NSTAGE 3
#define THREADS 256

// (1/0.07) * log2(e): fold temperature + exp->exp2 into one multiplier
static __device__ __constant__ float kTempInvLog2e = 20.6099131838246f;

// ---------------- scratch (no runtime allocation) ----------------
__device__ __half g_fa[(size_t)NROWS * DDIM];   // normalized A, fp16
__device__ __half g_fb[(size_t)NROWS * DDIM];   // normalized B, fp16
__device__ double g_pos[NROWS];
__device__ double g_neg[NROWS];
__device__ double g_loss;

// ---------------- SMEM layout ----------------
#define A_BYTES (BM * 128)            // 16384
#define B_BYTES (BN * 128)            // 16384
#define STAGE_B (A_BYTES + B_BYTES)   // 32768
#define AUX_BASE (NSTAGE * STAGE_B)   // 98304
#define AUX_SLA  (AUX_BASE)           // 128*4
#define AUX_SLB  (AUX_BASE + 512)     // 128*4
#define AUX_SPOS (AUX_BASE + 1024)    // 128*4
#define AUX_SNEG (AUX_BASE + 1536)    // 128*4
#define SMEM_TOTAL (AUX_BASE + 2048)  // 100352  (x2 CTAs = 200704 <= 228KB)

#define SWZ(o) ((o) ^ (((o) >> 3) & 0x70))

__device__ __forceinline__ uint32_t smem_u32(const void* p) {
    uint32_t a;
    asm("{ .reg .u64 t; cvta.to.shared.u64 t, %1; cvt.u32.u64 %0, t; }"
        : "=r"(a) : "l"(p));
    return a;
}

// Guaranteed MUFU.EX2 regardless of -use_fast_math
__device__ __forceinline__ float ex2_approx(float x) {
    float r;
    asm("ex2.approx.ftz.f32 %0, %1;" : "=f"(r) : "f"(x));
    return r;
}

#define LDSM_X4(r0, r1, r2, r3, addr) \
    asm volatile("ldmatrix.sync.aligned.m8n8.x4.shared.b16 {%0,%1,%2,%3}, [%4];" \
                 : "=r"(r0), "=r"(r1), "=r"(r2), "=r"(r3) : "r"(addr))

#define MMA16816(c, a, b0, b1) \
    asm volatile("mma.sync.aligned.m16n8k16.row.col.f32.f16.f16.f32 " \
                 "{%0,%1,%2,%3}, {%4,%5,%6,%7}, {%8,%9}, {%0,%1,%2,%3};" \
                 : "+f"((c)[0]), "+f"((c)[1]), "+f"((c)[2]), "+f"((c)[3]) \
                 : "r"((a)[0]), "r"((a)[1]), "r"((a)[2]), "r"((a)[3]), \
                   "r"(b0), "r"(b1))

#define CP_ASYNC16(dst, src) \
    asm volatile("cp.async.cg.shared.global [%0], [%1], 16;" :: "r"(dst), "l"(src))
#define CP_COMMIT() asm volatile("cp.async.commit_group;" ::: "memory")

// ---------------------------------------------------------------------------
// L2 normalize + fp16 convert + accumulator zeroing.
// 2*NROWS blocks, 256 threads, 4 floats/thread.
// ---------------------------------------------------------------------------
__global__ void normalize_kernel(const float* __restrict__ A,
                                 const float* __restrict__ B) {
    int row = blockIdx.x;
    const float* src;
    __half* dst;
    if (row < NROWS) {
        src = A + (size_t)row * DDIM;
        dst = g_fa + (size_t)row * DDIM;
        if (threadIdx.x == 0) { g_pos[row] = 0.0; g_neg[row] = 0.0; }
        if (row == 0 && threadIdx.x == 1) g_loss = 0.0;
    } else {
        int r = row - NROWS;
        src = B + (size_t)r * DDIM;
        dst = g_fb + (size_t)r * DDIM;
    }
    int t = threadIdx.x;
    float4 v = reinterpret_cast<const float4*>(src)[t];
    float s = v.x * v.x + v.y * v.y + v.z * v.z + v.w * v.w;
    #pragma unroll
    for (int off = 16; off > 0; off >>= 1)
        s += __shfl_xor_sync(0xffffffffu, s, off);
    __shared__ float ws[8];
    if ((t & 31) == 0) ws[t >> 5] = s;
    __syncthreads();
    if (t < 32) {
        float x = (t < 8) ? ws[t] : 0.0f;
        #pragma unroll
        for (int off = 4; off > 0; off >>= 1)
            x += __shfl_xor_sync(0xffffffffu, x, off);
        if (t == 0) ws[0] = x;
    }
    __syncthreads();
    float scale = 1.0f / fmaxf(sqrtf(ws[0]), 1e-12f);

    __half2 h0 = __floats2half2_rn(v.x * scale, v.y * scale);
    __half2 h1 = __floats2half2_rn(v.z * scale, v.w * scale);
    __half2* p = reinterpret_cast<__half2*>(dst + t * 4);
    p[0] = h0;
    p[1] = h1;
}

// ---------------------------------------------------------------------------
// fp16 mma.sync GEMM (128x128 CTA tile, 2 CTAs/SM) + fused exp/mask epilogue
// Prefetch cp.asyncs interleaved into the compute (2 per ks-step) to avoid
// post-barrier front-batched load bursts (cross-CTA L1tex contention).
// ---------------------------------------------------------------------------
extern __shared__ __align__(1024) char smem[];

// warp tile 32(M) x 64(N): wm = wid>>1 (0..3), wn = wid&1 (0..1)
template <bool PRE>
__device__ __forceinline__ void compute_chunk(uint32_t aBase0, uint32_t aBase1,
                                              uint32_t bBase0, uint32_t bBase1,
                                              uint32_t bBase2, uint32_t bBase3,
                                              float (&acc)[2][8][4],
                                              uint32_t dstA, uint32_t dstB,
                                              const __half* srcA,
                                              const __half* srcB) {
    #pragma unroll
    for (int ks = 0; ks < 4; ks++) {
        if (PRE) {  // 2 of the 8 prefetch cp.asyncs per ks-step
            CP_ASYNC16(dstA + ks * 4096, srcA + (size_t)ks * 32 * DDIM);
            CP_ASYNC16(dstB + ks * 4096, srcB + (size_t)ks * 32 * DDIM);
        }
        const uint32_t cb = ks * 32;   // XOR-offset within swizzled row
        uint32_t a[2][4];
        LDSM_X4(a[0][0], a[0][1], a[0][2], a[0][3], aBase0 ^ cb);
        LDSM_X4(a[1][0], a[1][1], a[1][2], a[1][3], aBase1 ^ cb);
        uint32_t b0, b1, b2, b3;
        LDSM_X4(b0, b1, b2, b3, bBase0 ^ cb);
        MMA16816(acc[0][0], a[0], b0, b2);
        MMA16816(acc[0][1], a[0], b1, b3);
        MMA16816(acc[1][0], a[1], b0, b2);
        MMA16816(acc[1][1], a[1], b1, b3);
        LDSM_X4(b0, b1, b2, b3, bBase1 ^ cb);
        MMA16816(acc[0][2], a[0], b0, b2);
        MMA16816(acc[0][3], a[0], b1, b3);
        MMA16816(acc[1][2], a[1], b0, b2);
        MMA16816(acc[1][3], a[1], b1, b3);
        LDSM_X4(b0, b1, b2, b3, bBase2 ^ cb);
        MMA16816(acc[0][4], a[0], b0, b2);
        MMA16816(acc[0][5], a[0], b1, b3);
        MMA16816(acc[1][4], a[1], b0, b2);
        MMA16816(acc[1][5], a[1], b1, b3);
        LDSM_X4(b0, b1, b2, b3, bBase3 ^ cb);
        MMA16816(acc[0][6], a[0], b0, b2);
        MMA16816(acc[0][7], a[0], b1, b3);
        MMA16816(acc[1][6], a[1], b0, b2);
        MMA16816(acc[1][7], a[1], b1, b3);
    }
    if (PRE) CP_COMMIT();
}

__global__ __launch_bounds__(THREADS, 2)
void gemm_mma_kernel(const int* __restrict__ la, const int* __restrict__ lb) {
    const int tid  = threadIdx.x;
    const int lane = tid & 31;
    const int wid  = tid >> 5;
    const int wm   = wid >> 1;       // 4 warps along M (32 rows each)
    const int wn   = wid & 1;        // 2 warps along N (64 cols each)
    const int bm0  = blockIdx.y * BM;
    const int bn0  = blockIdx.x * BN;

    int* sla = (int*)(smem + AUX_SLA);
    int* slb = (int*)(smem + AUX_SLB);
    float* spos = (float*)(smem + AUX_SPOS);
    float* sneg = (float*)(smem + AUX_SNEG);

    if (tid < BM) {
        sla[tid] = la[bm0 + tid];
        slb[tid] = lb[bn0 + tid];
        spos[tid] = 0.0f;
        sneg[tid] = 0.0f;
    }

    uint32_t sbase = smem_u32(smem);

    // ---- per-thread cp.async offsets (row = tid>>3 in [0,32), u = tid&7) ----
    const int ld_r = tid >> 3;
    const int ld_u = tid & 7;
    const uint32_t ld_off = SWZ(ld_r * 128 + ld_u * 16);
    const __half* srcA = g_fa + (size_t)(bm0 + ld_r) * DDIM + ld_u * 8;
    const __half* srcB = g_fb + (size_t)(bn0 + ld_r) * DDIM + ld_u * 8;

    // ---- per-thread ldsm base addresses ----
    // SWZ(row*128 + cb) == row*128 + (cb ^ (row&7)*16) for cb in bits [4:7)
    // A warp tile = 32 rows at wm*32; B warp tile = 64 rows at wn*64.
    const int rl = lane & 15;
    const int ch = lane >> 4;
    const int ar0 = wm * 32 + rl;
    const int ar1 = wm * 32 + 16 + rl;
    const int br0 = wn * 64 + rl;
    const uint32_t chx = (uint32_t)(ch * 16);
    const uint32_t aOff0 = (uint32_t)(ar0 * 128) + (((uint32_t)(ar0 & 7) * 16) ^ chx);
    const uint32_t aOff1 = (uint32_t)(ar1 * 128) + (((uint32_t)(ar1 & 7) * 16) ^ chx);
    const uint32_t bOff0 = (uint32_t)(br0 * 128) + (((uint32_t)(br0 & 7) * 16) ^ chx);
    const uint32_t bStep = 16 * 128;   // row&7 repeats every 16 rows

    float acc[2][8][4];
    #pragma unroll
    for (int i = 0; i < 2; i++)
        #pragma unroll
        for (int j = 0; j < 8; j++)
            #pragma unroll
            for (int v = 0; v < 4; v++)
                acc[i][j][v] = 0.0f;

    // prologue: chunks 0 and 1 in flight (pipeline fill; bursts OK here)
    {
        uint32_t dA0 = sbase + ld_off, dB0 = sbase + A_BYTES + ld_off;
        #pragma unroll
        for (int it = 0; it < 4; it++) {
            CP_ASYNC16(dA0 + it * 4096, srcA + (size_t)it * 32 * DDIM);
            CP_ASYNC16(dB0 + it * 4096, srcB + (size_t)it * 32 * DDIM);
        }
        CP_COMMIT();
        uint32_t dA1 = dA0 + STAGE_B, dB1 = dB0 + STAGE_B;
        #pragma unroll
        for (int it = 0; it < 4; it++) {
            CP_ASYNC16(dA1 + it * 4096, srcA + BK + (size_t)it * 32 * DDIM);
            CP_ASYNC16(dB1 + it * 4096, srcB + BK + (size_t)it * 32 * DDIM);
        }
        CP_COMMIT();
    }

    // one sync per chunk; prefetch depth 2 over 3 buffers, loads interleaved
    // into compute. iter c: pending groups {c, c+1}; wait_group 1 retires c.
    // chunk c+2 -> buffer (c+2)%3 == buffer consumed at iter c-1 (all readers
    // passed this iteration's barrier).
    #pragma unroll 1
    for (int c = 0; c < NCHUNK - 2; c++) {
        asm volatile("cp.async.wait_group 1;" ::: "memory");
        __syncthreads();
        uint32_t aB = sbase + (c % NSTAGE) * STAGE_B;
        uint32_t bB = aB + A_BYTES;
        uint32_t st = ((c + 2) % NSTAGE) * STAGE_B;
        compute_chunk<true>(aB + aOff0, aB + aOff1,
                            bB + bOff0, bB + bOff0 + bStep,
                            bB + bOff0 + 2 * bStep, bB + bOff0 + 3 * bStep, acc,
                            sbase + st + ld_off, sbase + st + A_BYTES + ld_off,
                            srcA + (c + 2) * BK, srcB + (c + 2) * BK);
    }
    {   // chunk 14: pending {14, 15}
        asm volatile("cp.async.wait_group 1;" ::: "memory");
        __syncthreads();
        uint32_t aB = sbase + ((NCHUNK - 2) % NSTAGE) * STAGE_B;
        uint32_t bB = aB + A_BYTES;
        compute_chunk<false>(aB + aOff0, aB + aOff1,
                             bB + bOff0, bB + bOff0 + bStep,
                             bB + bOff0 + 2 * bStep, bB + bOff0 + 3 * bStep, acc,
                             0, 0, nullptr, nullptr);
    }
    {   // chunk 15: pending {15}
        asm volatile("cp.async.wait_group 0;" ::: "memory");
        __syncthreads();
        uint32_t aB = sbase + ((NCHUNK - 1) % NSTAGE) * STAGE_B;
        uint32_t bB = aB + A_BYTES;
        compute_chunk<false>(aB + aOff0, aB + aOff1,
                             bB + bOff0, bB + bOff0 + bStep,
                             bB + bOff0 + 2 * bStep, bB + bOff0 + 3 * bStep, acc,
                             0, 0, nullptr, nullptr);
    }

    // ----- epilogue: exp + label mask + row sums -----
    // clip to [-50,50] omitted: |sim| <= 1/0.07 = 14.29 for unit rows.
    // exp(sim) = ex2.approx(acc * (kTempInv*log2e)) -- one FMUL + MUFU.EX2.
    const int g  = lane >> 2;
    const int t4 = lane & 3;

    int rowlab[4];
    #pragma unroll
    for (int i = 0; i < 2; i++) {
        rowlab[2 * i + 0] = sla[wm * 32 + i * 16 + g];
        rowlab[2 * i + 1] = sla[wm * 32 + i * 16 + g + 8];
    }
    int collab[16];
    #pragma unroll
    for (int j = 0; j < 8; j++) {
        collab[2 * j + 0] = slb[wn * 64 + j * 8 + t4 * 2 + 0];
        collab[2 * j + 1] = slb[wn * 64 + j * 8 + t4 * 2 + 1];
    }

    float prow[4], nrow[4];
    #pragma unroll
    for (int k = 0; k < 4; k++) { prow[k] = 0.0f; nrow[k] = 0.0f; }

    #pragma unroll
    for (int i = 0; i < 2; i++)
        #pragma unroll
        for (int j = 0; j < 8; j++)
            #pragma unroll
            for (int v = 0; v < 4; v++) {
                float e = ex2_approx(acc[i][j][v] * kTempInvLog2e);
                int h = v >> 1;
                nrow[2 * i + h] += e;
                if (collab[2 * j + (v & 1)] == rowlab[2 * i + h])
                    prow[2 * i + h] += e;
            }

    // reduce across the 4 lanes of each quad (same row, different cols)
    #pragma unroll
    for (int off = 1; off <= 2; off <<= 1)
        #pragma unroll
        for (int k = 0; k < 4; k++) {
            prow[k] += __shfl_xor_sync(0xffffffffu, prow[k], off);
            nrow[k] += __shfl_xor_sync(0xffffffffu, nrow[k], off);
        }

    if (t4 == 0) {
        #pragma unroll
        for (int k = 0; k < 4; k++) {
            int row = wm * 32 + (k >> 1) * 16 + g + (k & 1) * 8;
            atomicAdd(&spos[row], prow[k]);
            atomicAdd(&sneg[row], nrow[k]);
        }
    }
    __syncthreads();
    if (tid < BM) {
        atomicAdd(&g_pos[bm0 + tid], (double)spos[tid]);
        atomicAdd(&g_neg[bm0 + tid], (double)sneg[tid]);
    }
}

// ---------------------------------------------------------------------------
// finalize stage 1: 16 blocks x 512 threads, partial sums -> atomic double
// ---------------------------------------------------------------------------
__global__ void finalize1_kernel() {
    int t = blockIdx.x * blockDim.x + threadIdx.x;  // 8192 threads total
    double p = g_pos[t];
    if (p < 1e-8) p = 1e-8;
    double local = (double)logf((float)(p / g_neg[t]));
    #pragma unroll
    for (int off = 16; off > 0; off >>= 1)
        local += __shfl_xor_sync(0xffffffffu, local, off);
    __shared__ double ws[16];
    int lt = threadIdx.x;
    if ((lt & 31) == 0) ws[lt >> 5] = local;
    __syncthreads();
    if (lt < 16) {
        double x = ws[lt];
        #pragma unroll
        for (int off = 8; off > 0; off >>= 1)
            x += __shfl_xor_sync(0xffffffffu, x, off);
        if (lt == 0) atomicAdd(&g_loss, x);
    }
}

__global__ void finalize2_kernel(float* __restrict__ out) {
    out[0] = (float)(-g_loss / (double)NROWS);
}

// ---------------------------------------------------------------------------
extern "C" void kernel_launch(void* const* d_in, const int* in_sizes, int n_in,
                              void* d_out, int out_size) {
    const float* fa = (const float*)d_in[0];
    const float* fb = (const float*)d_in[1];
    const int*   la = (const int*)d_in[2];
    const int*   lb = (const int*)d_in[3];
    float* out = (float*)d_out;

    cudaFuncSetAttribute(gemm_mma_kernel,
                         cudaFuncAttributeMaxDynamicSharedMemorySize, SMEM_TOTAL);

    normalize_kernel<<<2 * NROWS, 256>>>(fa, fb);
    dim3 grid(NROWS / BN, NROWS / BM);
    gemm_mma_kernel<<<grid, THREADS, SMEM_TOTAL>>>(la, lb);
    finalize1_kernel<<<16, 512>>>();
    finalize2_kernel<<<1, 1>>>(out);
}